// round 15
// baseline (speedup 1.0000x reference)
#include <cuda_runtime.h>
#include <cuda_bf16.h>

// Problem constants (match setup_inputs: P=1024, M=64, R=64)
#define P 1024
#define MDIM 64
#define RDIM 64
#define NTHR 256
#define PF 2       // software-pipeline depth (float4 buffers in flight)
#define QJ  256    // j's per stream block (quarter row)
#define NPRE    (P / 8)   // 128 precompute blocks (front of grid, wave-1)
#define NSTREAM (P * 4)   // 4096 stream blocks
#define NHSUM   (P / 8)   // 128 hsum blocks (tail of grid, spin-gated)

// Allocation-free scratch (__device__ globals; zero-init at load, self-resetting)
__device__ float g_hi[P];
__device__ float g_hj[P];
__device__ float g_attn[P * P];   // 4 MB: RAW dots -> (in place) FINAL attn
__device__ int   g_rowcnt[P];     // quarters-done per row
__device__ int   g_rowdone[P];    // attn row finalized
__device__ int   g_pre;           // precompute-ready counter
__device__ int   g_hsum_cnt;      // finished hsum blocks (for g_pre reset)

// ---------------------------------------------------------------------------
// ONE fused kernel, three roles by blockIdx.x:
//   [0, 128):        precompute hi/hj (warp-per-row). Wave-1, never waits.
//   [128, 4224):     stream blocks: (row i, quarter q) stream 64 KB of rela,
//                    write raw dots; last quarter of a row does the full
//                    softmax in place and sets g_rowdone[i].
//   [4224, 4352):    hsum blocks: 8 rows x all 1024 j. Spin on g_rowdone for
//                    their 8 rows (all stream blocks are dispatched earlier ->
//                    progress guaranteed), then attn @ hidden with plain
//                    stores (each output owned by exactly one block).
// ---------------------------------------------------------------------------
__global__ __launch_bounds__(NTHR, 7) void fused_kernel(
    const float* __restrict__ rela,
    const float* __restrict__ hidden,
    const int*   __restrict__ nei,
    const float* __restrict__ W,
    const float* __restrict__ bptr,
    float* __restrict__ out)
{
    // Shared pool unioned across roles (20.3 KB):
    //   stream: part = pool[0..1279], red = pool[1280..1287]
    //   hsum:   sat  = pool[0..1023] ([8][128]), partb = pool[1024..5119]
    __shared__ float pool[5184];
    __shared__ int   s_old;

    const int tid  = threadIdx.x;
    const int warp = tid >> 5;
    const int lane = tid & 31;

    // ================= role 1: precompute =================
    if (blockIdx.x < NPRE) {
        const int row = blockIdx.x * 8 + warp;

        float2 h = reinterpret_cast<const float2*>(hidden + (size_t)row * MDIM)[lane];
        float wi0 = W[RDIM + lane * 2];
        float wi1 = W[RDIM + lane * 2 + 1];
        float wj0 = W[RDIM + MDIM + lane * 2];
        float wj1 = W[RDIM + MDIM + lane * 2 + 1];

        float si = h.x * wi0 + h.y * wi1;
        float sj = h.x * wj0 + h.y * wj1;
        #pragma unroll
        for (int off = 16; off >= 1; off >>= 1) {
            si += __shfl_xor_sync(0xFFFFFFFFu, si, off);
            sj += __shfl_xor_sync(0xFFFFFFFFu, sj, off);
        }
        if (lane == 0) {
            g_hi[row] = si;
            g_hj[row] = sj;
        }
        __threadfence();
        __syncthreads();
        if (tid == 0) atomicAdd(&g_pre, 1);
        return;
    }

    // ================= role 2: stream + in-place softmax =================
    if (blockIdx.x < NPRE + NSTREAM) {
        float* part = pool;            // [QJ*5] padded partials
        float* red  = pool + 1280;     // [8]

        const int half = (lane >> 4);
        const int lh   = lane & 15;
        const int hwid = warp * 2 + half;

        const int sid = blockIdx.x - NPRE;
        const int i   = sid >> 2;
        const int q   = sid & 3;
        const int j0  = q * QJ;

        {
            const float4 wv = __ldg(&reinterpret_cast<const float4*>(W)[lh]);
            const float4* p = reinterpret_cast<const float4*>(rela + (size_t)i * (P * RDIM))
                            + (size_t)(j0 + hwid) * 16 + lh;
            float4 buf[PF];
            #pragma unroll
            for (int qq = 0; qq < PF; qq++) buf[qq] = __ldcs(p + qq * 256);
            p += PF * 256;

            #pragma unroll
            for (int kk = 0; kk < (QJ / 16) / PF; kk++) {
                #pragma unroll
                for (int qq = 0; qq < PF; qq++) {
                    float4 v = buf[qq];
                    if (kk < (QJ / 16) / PF - 1) buf[qq] = __ldcs(p + qq * 256);
                    float s = fmaf(v.x, wv.x, fmaf(v.y, wv.y, fmaf(v.z, wv.z, v.w * wv.w)));
                    s += __shfl_xor_sync(0xFFFFFFFFu, s, 8);     // 16 -> 8
                    s += __shfl_xor_sync(0xFFFFFFFFu, s, 4);     // 8 -> 4 partials
                    const int jl = (kk * PF + qq) * 16 + hwid;
                    if (lh < 4) part[jl * 5 + lh] = s;           // pad 5: conflict-free
                }
                p += PF * 256;
            }
        }
        __syncthreads();

        // write RAW dot: thread tid <-> local j
        {
            const float* pj = &part[tid * 5];
            float s = (pj[0] + pj[1]) + (pj[2] + pj[3]);
            g_attn[(size_t)i * P + j0 + tid] = s;
        }

        __threadfence();
        __syncthreads();
        if (tid == 0) s_old = atomicAdd(&g_rowcnt[i], 1);
        __syncthreads();
        if (s_old != 3) return;

        // last quarter of row i: full softmax in place
        if (tid == 0) {
            while (*(volatile int*)&g_pre < NPRE) __nanosleep(64);
        }
        __syncthreads();
        __threadfence();

        float4 v  = reinterpret_cast<const float4*>(g_attn + (size_t)i * P)[tid];
        int4  n4  = reinterpret_cast<const int4*>(nei + (size_t)i * P)[tid];
        float4 hj = reinterpret_cast<const float4*>(g_hj)[tid];
        const float hb = g_hi[i] + bptr[0];

        v.x = (n4.x > 0) ? (v.x + hj.x + hb) : 0.0f;  if (v.x == 0.0f) v.x = -1e-6f;
        v.y = (n4.y > 0) ? (v.y + hj.y + hb) : 0.0f;  if (v.y == 0.0f) v.y = -1e-6f;
        v.z = (n4.z > 0) ? (v.z + hj.z + hb) : 0.0f;  if (v.z == 0.0f) v.z = -1e-6f;
        v.w = (n4.w > 0) ? (v.w + hj.w + hb) : 0.0f;  if (v.w == 0.0f) v.w = -1e-6f;

        float mx = fmaxf(fmaxf(v.x, v.y), fmaxf(v.z, v.w));
        #pragma unroll
        for (int off = 16; off >= 1; off >>= 1)
            mx = fmaxf(mx, __shfl_xor_sync(0xFFFFFFFFu, mx, off));
        if (lane == 0) red[warp] = mx;
        __syncthreads();
        {
            float m = red[0];
            #pragma unroll
            for (int w = 1; w < 8; w++) m = fmaxf(m, red[w]);
            mx = m;
        }
        __syncthreads();

        float4 e;
        e.x = __expf(v.x - mx);
        e.y = __expf(v.y - mx);
        e.z = __expf(v.z - mx);
        e.w = __expf(v.w - mx);
        float sum = (e.x + e.y) + (e.z + e.w);
        #pragma unroll
        for (int off = 16; off >= 1; off >>= 1)
            sum += __shfl_xor_sync(0xFFFFFFFFu, sum, off);
        if (lane == 0) red[warp] = sum;
        __syncthreads();
        float inv;
        {
            float s = 0.0f;
            #pragma unroll
            for (int w = 0; w < 8; w++) s += red[w];
            inv = 1.0f / s;
        }

        float4 a;
        a.x = (n4.x > 0) ? e.x * inv : 0.0f;
        a.y = (n4.y > 0) ? e.y * inv : 0.0f;
        a.z = (n4.z > 0) ? e.z * inv : 0.0f;
        a.w = (n4.w > 0) ? e.w * inv : 0.0f;
        reinterpret_cast<float4*>(g_attn + (size_t)i * P)[tid] = a;

        __threadfence();
        __syncthreads();
        if (tid == 0) *(volatile int*)&g_rowdone[i] = 1;
        return;
    }

    // ================= role 3: hsum (spin-gated tail) =================
    float* sat   = pool;          // [8][128] attn chunk
    float* partb = pool + 1024;   // [8][8][64] jg-partials

    const int hb = blockIdx.x - (NPRE + NSTREAM);   // 0..127
    const int i0 = hb * 8;

    if (tid < 8) {
        while (*(volatile int*)&g_rowdone[i0 + tid] == 0) __nanosleep(128);
    }
    __syncthreads();
    __threadfence();

    const int d2 = tid & 31;        // float2 slot: d = 2*d2, 2*d2+1
    const int jg = warp;            // 0..7, 16 j per chunk
    const float2* hidden2 = reinterpret_cast<const float2*>(hidden);

    float2 acc[8];
    #pragma unroll
    for (int r = 0; r < 8; r++) acc[r] = make_float2(0.0f, 0.0f);

    #pragma unroll 1
    for (int c = 0; c < 8; c++) {
        const int j0 = c * 128;
        // stage attn chunk [8][128]: 1 float4 per thread, coalesced
        {
            const int r  = tid >> 5;
            const int c4 = tid & 31;
            reinterpret_cast<float4*>(sat + r * 128)[c4] =
                reinterpret_cast<const float4*>(g_attn + (size_t)(i0 + r) * P + j0)[c4];
        }
        __syncthreads();

        #pragma unroll
        for (int b4 = 0; b4 < 4; b4++) {
            const int jl = jg * 16 + b4 * 4;    // local j base
            float2 h0 = hidden2[(size_t)(j0 + jl + 0) * 32 + d2];
            float2 h1 = hidden2[(size_t)(j0 + jl + 1) * 32 + d2];
            float2 h2 = hidden2[(size_t)(j0 + jl + 2) * 32 + d2];
            float2 h3 = hidden2[(size_t)(j0 + jl + 3) * 32 + d2];
            #pragma unroll
            for (int r = 0; r < 8; r++) {
                float4 a4 = *reinterpret_cast<const float4*>(sat + r * 128 + jl); // LDS broadcast
                acc[r].x = fmaf(a4.x, h0.x, acc[r].x); acc[r].y = fmaf(a4.x, h0.y, acc[r].y);
                acc[r].x = fmaf(a4.y, h1.x, acc[r].x); acc[r].y = fmaf(a4.y, h1.y, acc[r].y);
                acc[r].x = fmaf(a4.z, h2.x, acc[r].x); acc[r].y = fmaf(a4.z, h2.y, acc[r].y);
                acc[r].x = fmaf(a4.w, h3.x, acc[r].x); acc[r].y = fmaf(a4.w, h3.y, acc[r].y);
            }
        }
        __syncthreads();   // before next stage overwrites sat
    }

    // jg-partials -> single reduce -> plain stores (block owns its outputs)
    #pragma unroll
    for (int r = 0; r < 8; r++)
        reinterpret_cast<float2*>(partb + (jg * 8 + r) * 64)[d2] = acc[r];
    __syncthreads();

    #pragma unroll
    for (int oo = 0; oo < 2; oo++) {
        const int o = oo * NTHR + tid;
        const int r = o >> 6;
        const int d = o & 63;
        float s = ((partb[(0 * 8 + r) * 64 + d] + partb[(1 * 8 + r) * 64 + d])
                +  (partb[(2 * 8 + r) * 64 + d] + partb[(3 * 8 + r) * 64 + d]))
                + ((partb[(4 * 8 + r) * 64 + d] + partb[(5 * 8 + r) * 64 + d])
                +  (partb[(6 * 8 + r) * 64 + d] + partb[(7 * 8 + r) * 64 + d]));
        out[(size_t)(i0 + r) * MDIM + d] = s;
    }

    // reset per-row state for the next graph replay
    if (tid < 8) {
        g_rowdone[i0 + tid] = 0;
        g_rowcnt[i0 + tid]  = 0;
    }
    __threadfence();
    __syncthreads();
    if (tid == 0) {
        int old = atomicAdd(&g_hsum_cnt, 1);
        if (old == NHSUM - 1) {          // last hsum block: nobody reads g_pre anymore
            g_pre = 0;
            g_hsum_cnt = 0;
            __threadfence();
        }
    }
}

// ---------------------------------------------------------------------------
// Inputs (metadata order): 0 hidden_state f32[1024,64], 1 rela_state f32[1024,1024,64],
// 2 corr_index f32 (UNUSED), 3 nei_index i32[1024,1024], 4 W f32[192], 5 b f32[1].
// Output: f32[1024,64].
// ---------------------------------------------------------------------------
extern "C" void kernel_launch(void* const* d_in, const int* in_sizes, int n_in,
                              void* d_out, int out_size)
{
    const float* hidden = (const float*)d_in[0];
    const float* rela   = (const float*)d_in[1];
    const int*   nei    = (const int*)  d_in[3];
    const float* W      = (const float*)d_in[4];
    const float* b      = (const float*)d_in[5];
    float*       out    = (float*)d_out;

    fused_kernel<<<NPRE + NSTREAM + NHSUM, NTHR>>>(rela, hidden, nei, W, b, out);
}

// round 16
// speedup vs baseline: 2.3051x; 2.3051x over previous
#include <cuda_runtime.h>
#include <cuda_bf16.h>

// Problem constants (match setup_inputs: P=1024, M=64, R=64)
#define P 1024
#define MDIM 64
#define RDIM 64
#define NTHR 256
#define PF 2       // software-pipeline depth (float4 buffers in flight)
#define QJ  256    // j's per stream block (quarter row)
#define NPRE    (P / 8)   // 128 precompute blocks at the FRONT of the grid
#define NSTREAM (P * 4)   // 4096 stream blocks

// hsum tiling
#define ITILE 8
#define JTILE 128
#define NJT   (P / JTILE)   // 8
#define NIT   (P / ITILE)   // 128

// Allocation-free scratch (__device__ globals)
__device__ float g_hi[P];
__device__ float g_hj[P];
__device__ float g_attn[P * P];   // 4 MB: RAW dots -> (in place) FINAL attn
__device__ int   g_rowcnt[P];     // quarters-done per row (reset by hsum)
__device__ int   g_pre;           // precompute-ready counter (reset by hsum)

// ---------------------------------------------------------------------------
// Kernel A (unchanged from the 51.9us best): one grid, three roles.
//   blocks [0, 128):    precompute hi/hj (warp-per-row), zero d_out, signal.
//   blocks [128, 4224): (row i, quarter q) stream 64 KB of rela via __ldcs,
//                       write raw dots; the row's 4th-quarter block computes
//                       the FULL softmax in place — hidden under the stream.
// ---------------------------------------------------------------------------
__global__ __launch_bounds__(NTHR, 8) void stream_kernel(
    const float* __restrict__ rela,
    const float* __restrict__ hidden,
    const int*   __restrict__ nei,
    const float* __restrict__ W,
    const float* __restrict__ bptr,
    float* __restrict__ out)
{
    const int tid  = threadIdx.x;
    const int warp = tid >> 5;
    const int lane = tid & 31;

    if (blockIdx.x < NPRE) {
        // ---- precompute branch: hi/hj + zero d_out + ready signal ----
        const int pid = blockIdx.x;
        const int row = pid * 8 + warp;
        const int gid = pid * 256 + tid;             // 32768 threads

        reinterpret_cast<float2*>(out)[gid] = make_float2(0.0f, 0.0f);

        float2 h = reinterpret_cast<const float2*>(hidden + (size_t)row * MDIM)[lane];
        float wi0 = W[RDIM + lane * 2];
        float wi1 = W[RDIM + lane * 2 + 1];
        float wj0 = W[RDIM + MDIM + lane * 2];
        float wj1 = W[RDIM + MDIM + lane * 2 + 1];

        float si = h.x * wi0 + h.y * wi1;
        float sj = h.x * wj0 + h.y * wj1;
        #pragma unroll
        for (int off = 16; off >= 1; off >>= 1) {
            si += __shfl_xor_sync(0xFFFFFFFFu, si, off);
            sj += __shfl_xor_sync(0xFFFFFFFFu, sj, off);
        }
        if (lane == 0) {
            g_hi[row] = si;
            g_hj[row] = sj;
        }
        __threadfence();
        __syncthreads();
        if (tid == 0) atomicAdd(&g_pre, 1);
        return;
    }

    // ---- streaming branch ----
    __shared__ float part[QJ * 5];       // 4 partials per local j, padded (5 KB)
    __shared__ float red[8];
    __shared__ int   s_old;

    const int half = (lane >> 4);
    const int lh   = lane & 15;          // lane within half-warp
    const int hwid = warp * 2 + half;    // 0..15 half-warp id

    const int sid = blockIdx.x - NPRE;
    const int i   = sid >> 2;
    const int q   = sid & 3;
    const int j0  = q * QJ;

    {
        const float4 wv = __ldg(&reinterpret_cast<const float4*>(W)[lh]);
        const float4* p = reinterpret_cast<const float4*>(rela + (size_t)i * (P * RDIM))
                        + (size_t)(j0 + hwid) * 16 + lh;
        float4 buf[PF];
        #pragma unroll
        for (int qq = 0; qq < PF; qq++) buf[qq] = __ldcs(p + qq * 256);
        p += PF * 256;

        #pragma unroll
        for (int kk = 0; kk < (QJ / 16) / PF; kk++) {
            #pragma unroll
            for (int qq = 0; qq < PF; qq++) {
                float4 v = buf[qq];
                if (kk < (QJ / 16) / PF - 1) buf[qq] = __ldcs(p + qq * 256);
                float s = fmaf(v.x, wv.x, fmaf(v.y, wv.y, fmaf(v.z, wv.z, v.w * wv.w)));
                s += __shfl_xor_sync(0xFFFFFFFFu, s, 8);     // 16 -> 8
                s += __shfl_xor_sync(0xFFFFFFFFu, s, 4);     // 8 -> 4 partials
                const int jl = (kk * PF + qq) * 16 + hwid;
                if (lh < 4) part[jl * 5 + lh] = s;           // conflict-free (pad 5)
            }
            p += PF * 256;
        }
    }
    __syncthreads();

    // ---- finish: thread tid <-> local j = tid; write RAW dot ----
    {
        const float* pj = &part[tid * 5];          // stride 5: conflict-free
        float s = (pj[0] + pj[1]) + (pj[2] + pj[3]);
        g_attn[(size_t)i * P + j0 + tid] = s;      // coalesced 1 KB
    }

    // ---- quarter done: last block of the row does the FULL softmax ----
    __threadfence();
    __syncthreads();
    if (tid == 0) s_old = atomicAdd(&g_rowcnt[i], 1);
    __syncthreads();
    if (s_old != 3) return;

    if (tid == 0) {
        while (*(volatile int*)&g_pre < NPRE) __nanosleep(64);
    }
    __syncthreads();
    __threadfence();

    float4 v  = reinterpret_cast<const float4*>(g_attn + (size_t)i * P)[tid];
    int4  n4  = reinterpret_cast<const int4*>(nei + (size_t)i * P)[tid];
    float4 hj = reinterpret_cast<const float4*>(g_hj)[tid];
    const float hb = g_hi[i] + bptr[0];

    v.x = (n4.x > 0) ? (v.x + hj.x + hb) : 0.0f;  if (v.x == 0.0f) v.x = -1e-6f;
    v.y = (n4.y > 0) ? (v.y + hj.y + hb) : 0.0f;  if (v.y == 0.0f) v.y = -1e-6f;
    v.z = (n4.z > 0) ? (v.z + hj.z + hb) : 0.0f;  if (v.z == 0.0f) v.z = -1e-6f;
    v.w = (n4.w > 0) ? (v.w + hj.w + hb) : 0.0f;  if (v.w == 0.0f) v.w = -1e-6f;

    float mx = fmaxf(fmaxf(v.x, v.y), fmaxf(v.z, v.w));
    #pragma unroll
    for (int off = 16; off >= 1; off >>= 1)
        mx = fmaxf(mx, __shfl_xor_sync(0xFFFFFFFFu, mx, off));
    if (lane == 0) red[warp] = mx;
    __syncthreads();
    {
        float m = red[0];
        #pragma unroll
        for (int w = 1; w < 8; w++) m = fmaxf(m, red[w]);
        mx = m;
    }
    __syncthreads();

    float4 e;
    e.x = __expf(v.x - mx);
    e.y = __expf(v.y - mx);
    e.z = __expf(v.z - mx);
    e.w = __expf(v.w - mx);
    float sum = (e.x + e.y) + (e.z + e.w);
    #pragma unroll
    for (int off = 16; off >= 1; off >>= 1)
        sum += __shfl_xor_sync(0xFFFFFFFFu, sum, off);
    if (lane == 0) red[warp] = sum;
    __syncthreads();
    float inv;
    {
        float s = 0.0f;
        #pragma unroll
        for (int w = 0; w < 8; w++) s += red[w];
        inv = 1.0f / s;
    }

    float4 a;
    a.x = (n4.x > 0) ? e.x * inv : 0.0f;
    a.y = (n4.y > 0) ? e.y * inv : 0.0f;
    a.z = (n4.z > 0) ? e.z * inv : 0.0f;
    a.w = (n4.w > 0) ? e.w * inv : 0.0f;
    reinterpret_cast<float4*>(g_attn + (size_t)i * P)[tid] = a;
}

// ---------------------------------------------------------------------------
// Kernel B v2: H_sum = attn @ hidden. 128 i-tiles (8 rows) x 8 j-tiles = 1024
// blocks. Inner loop: 4 j per step, attn via warp-uniform float4 LDS
// broadcasts, hidden via 4 prefetched float2 -> ~1.2 instr/MAC.
// launch_bounds(256,5) caps regs at 51 -> 5 CTA/SM (62.5% occ).
// Resets counters for the next graph replay.
// ---------------------------------------------------------------------------
__global__ __launch_bounds__(NTHR, 5) void hsum_kernel(
    const float* __restrict__ hidden,
    float*       __restrict__ out)
{
    __shared__ float sat[ITILE * JTILE];           // 4 KB (attn tile)
    __shared__ float partb[8 * ITILE * MDIM];      // 16 KB

    const int tid = threadIdx.x;
    const int it  = blockIdx.x >> 3;          // 0..127
    const int jt  = blockIdx.x & 7;           // 0..7
    const int i0  = it * ITILE;
    const int j0  = jt * JTILE;

    // reset counters for the next replay (this kernel always runs last)
    if (jt == 0 && tid < ITILE) g_rowcnt[i0 + tid] = 0;
    if (blockIdx.x == 0 && tid == 0) g_pre = 0;

    // stage attn tile: 256 float4, 1 per thread, coalesced, plain copy
    {
        const int r  = tid >> 5;               // 0..7
        const int c4 = tid & 31;               // 32 float4 per row
        reinterpret_cast<float4*>(sat + r * JTILE)[c4] =
            reinterpret_cast<const float4*>(g_attn + (size_t)(i0 + r) * P + j0)[c4];
    }
    __syncthreads();

    // main: thread = (d-pair d2 = tid&31, j-group jg = warp of 16 j)
    const int d2 = tid & 31;                   // covers d = 2*d2, 2*d2+1
    const int jg = tid >> 5;                   // 0..7 (uniform per warp)
    const float2* hidden2 = reinterpret_cast<const float2*>(hidden);

    float2 acc[ITILE];
    #pragma unroll
    for (int r = 0; r < ITILE; r++) acc[r] = make_float2(0.0f, 0.0f);

    #pragma unroll 1
    for (int b4 = 0; b4 < 4; b4++) {
        const int jl = jg * 16 + b4 * 4;       // local j base (4 j per step)
        float2 h0 = hidden2[(size_t)(j0 + jl + 0) * 32 + d2];
        float2 h1 = hidden2[(size_t)(j0 + jl + 1) * 32 + d2];
        float2 h2 = hidden2[(size_t)(j0 + jl + 2) * 32 + d2];
        float2 h3 = hidden2[(size_t)(j0 + jl + 3) * 32 + d2];
        #pragma unroll
        for (int r = 0; r < ITILE; r++) {
            float4 a4 = *reinterpret_cast<const float4*>(sat + r * JTILE + jl); // broadcast
            acc[r].x = fmaf(a4.x, h0.x, acc[r].x); acc[r].y = fmaf(a4.x, h0.y, acc[r].y);
            acc[r].x = fmaf(a4.y, h1.x, acc[r].x); acc[r].y = fmaf(a4.y, h1.y, acc[r].y);
            acc[r].x = fmaf(a4.z, h2.x, acc[r].x); acc[r].y = fmaf(a4.z, h2.y, acc[r].y);
            acc[r].x = fmaf(a4.w, h3.x, acc[r].x); acc[r].y = fmaf(a4.w, h3.y, acc[r].y);
        }
    }

    #pragma unroll
    for (int r = 0; r < ITILE; r++)
        reinterpret_cast<float2*>(partb + (jg * ITILE + r) * MDIM)[d2] = acc[r];
    __syncthreads();

    // reduce 8 jg partials; 512 outputs, 2 per thread; d=o&63 -> conflict-free
    #pragma unroll
    for (int oo = 0; oo < 2; oo++) {
        const int o = oo * NTHR + tid;
        const int r = o >> 6;
        const int d = o & 63;
        float s = ((partb[(0 * ITILE + r) * MDIM + d] + partb[(1 * ITILE + r) * MDIM + d])
                +  (partb[(2 * ITILE + r) * MDIM + d] + partb[(3 * ITILE + r) * MDIM + d]))
                + ((partb[(4 * ITILE + r) * MDIM + d] + partb[(5 * ITILE + r) * MDIM + d])
                +  (partb[(6 * ITILE + r) * MDIM + d] + partb[(7 * ITILE + r) * MDIM + d]));
        atomicAdd(&out[(size_t)(i0 + r) * MDIM + d], s);
    }
}

// ---------------------------------------------------------------------------
// Inputs (metadata order): 0 hidden_state f32[1024,64], 1 rela_state f32[1024,1024,64],
// 2 corr_index f32 (UNUSED), 3 nei_index i32[1024,1024], 4 W f32[192], 5 b f32[1].
// Output: f32[1024,64].
// ---------------------------------------------------------------------------
extern "C" void kernel_launch(void* const* d_in, const int* in_sizes, int n_in,
                              void* d_out, int out_size)
{
    const float* hidden = (const float*)d_in[0];
    const float* rela   = (const float*)d_in[1];
    const int*   nei    = (const int*)  d_in[3];
    const float* W      = (const float*)d_in[4];
    const float* b      = (const float*)d_in[5];
    float*       out    = (float*)d_out;

    stream_kernel<<<NPRE + NSTREAM, NTHR>>>(rela, hidden, nei, W, b, out);
    hsum_kernel<<<NIT * NJT, NTHR>>>(hidden, out);
}